// round 14
// baseline (speedup 1.0000x reference)
#include <cuda_runtime.h>
#include <cuda_bf16.h>
#include <cstdint>
#include <math.h>

#define BATCH 8
#define SEQ   1024
#define HID   1024
#define NHEAD 16
#define HDIM  64
#define N3    3072
#define MROWS 8192
#define KDIM  1024

typedef unsigned long long u64;
typedef unsigned int u32;

// ---------------------------------------------------------------------------
// Scratch globals: bf16 2-way splits everywhere
// ---------------------------------------------------------------------------
__device__ __align__(16) __nv_bfloat16 g_Ah[MROWS*KDIM];
__device__ __align__(16) __nv_bfloat16 g_Am[MROWS*KDIM];
__device__ __align__(16) __nv_bfloat16 g_Wh[N3*KDIM];
__device__ __align__(16) __nv_bfloat16 g_Wm[N3*KDIM];

__device__ __align__(16) __nv_bfloat16 g_Qh[BATCH*NHEAD*SEQ*HDIM];
__device__ __align__(16) __nv_bfloat16 g_Qm[BATCH*NHEAD*SEQ*HDIM];
__device__ __align__(16) __nv_bfloat16 g_Kh[BATCH*NHEAD*SEQ*HDIM];
__device__ __align__(16) __nv_bfloat16 g_Km[BATCH*NHEAD*SEQ*HDIM];
__device__ __align__(16) __nv_bfloat16 g_Vh[BATCH*NHEAD*SEQ*HDIM];
__device__ __align__(16) __nv_bfloat16 g_Vm[BATCH*NHEAD*SEQ*HDIM];

// ---------------------------------------------------------------------------
// helpers
// ---------------------------------------------------------------------------
__device__ __forceinline__ u32 su32(const void* p) {
    u32 a;
    asm("{ .reg .u64 t; cvta.to.shared.u64 t, %1; cvt.u32.u64 %0, t; }" : "=r"(a) : "l"(p));
    return a;
}
__device__ __forceinline__ void cp16(u32 sm, const void* g) {
    asm volatile("cp.async.cg.shared.global [%0], [%1], 16;" :: "r"(sm), "l"(g));
}
__device__ __forceinline__ void cp_commit() {
    asm volatile("cp.async.commit_group;" ::: "memory");
}
__device__ __forceinline__ void cp_wait1() {
    asm volatile("cp.async.wait_group 1;" ::: "memory");
}
__device__ __forceinline__ void cp_wait0() {
    asm volatile("cp.async.wait_group 0;" ::: "memory");
}
__device__ __forceinline__ void ldsm4(u32* r, u32 addr) {
    asm volatile("ldmatrix.sync.aligned.m8n8.x4.shared.b16 {%0,%1,%2,%3}, [%4];"
                 : "=r"(r[0]), "=r"(r[1]), "=r"(r[2]), "=r"(r[3]) : "r"(addr));
}
__device__ __forceinline__ void ldsm4t(u32* r, u32 addr) {
    asm volatile("ldmatrix.sync.aligned.m8n8.x4.trans.shared.b16 {%0,%1,%2,%3}, [%4];"
                 : "=r"(r[0]), "=r"(r[1]), "=r"(r[2]), "=r"(r[3]) : "r"(addr));
}
__device__ __forceinline__ void mma16816(float* d, const u32* a, u32 b0, u32 b1) {
    asm volatile(
        "mma.sync.aligned.m16n8k16.row.col.f32.bf16.bf16.f32 "
        "{%0,%1,%2,%3}, {%4,%5,%6,%7}, {%8,%9}, {%0,%1,%2,%3};"
        : "+f"(d[0]), "+f"(d[1]), "+f"(d[2]), "+f"(d[3])
        : "r"(a[0]), "r"(a[1]), "r"(a[2]), "r"(a[3]), "r"(b0), "r"(b1));
}
__device__ __forceinline__ u32 cvtbf2(float lo, float hi) {
    u32 r; asm("cvt.rn.bf16x2.f32 %0, %1, %2;" : "=r"(r) : "f"(hi), "f"(lo)); return r;
}
__device__ __forceinline__ u32 resbf2(float lo, float hi, u32 h) {
    __nv_bfloat162 hb = *reinterpret_cast<__nv_bfloat162*>(&h);
    float2 hf = __bfloat1622float2(hb);
    return cvtbf2(lo - hf.x, hi - hf.y);
}

// ---------------------------------------------------------------------------
// split kernels: fp32 -> bf16 hi/mid
// ---------------------------------------------------------------------------
struct __align__(8) BF4 { __nv_bfloat16 a, b, c, d; };

__device__ __forceinline__ void split2(float x, __nv_bfloat16& h, __nv_bfloat16& m) {
    h = __float2bfloat16(x);
    m = __float2bfloat16(x - __bfloat162float(h));
}

__global__ void __launch_bounds__(256) split_hidden(const float* __restrict__ x) {
    size_t i = (size_t)blockIdx.x * 256 + threadIdx.x;
    float4 v = ((const float4*)x)[i];
    BF4 H, M;
    split2(v.x, H.a, M.a);
    split2(v.y, H.b, M.b);
    split2(v.z, H.c, M.c);
    split2(v.w, H.d, M.d);
    ((BF4*)g_Ah)[i] = H;
    ((BF4*)g_Am)[i] = M;
}

__global__ void __launch_bounds__(256) split_w(const float* __restrict__ w) {
    __shared__ float tile[64][65];
    const int n0 = blockIdx.x * 64, k0 = blockIdx.y * 64;
    const int tid = threadIdx.x;
    #pragma unroll
    for (int i = 0; i < 4; i++) {
        int idx = tid + i * 256;
        int r = idx >> 4, c4 = idx & 15;
        float4 v = *(const float4*)&w[(size_t)(k0 + r) * N3 + n0 + c4 * 4];
        tile[r][c4*4+0] = v.x; tile[r][c4*4+1] = v.y;
        tile[r][c4*4+2] = v.z; tile[r][c4*4+3] = v.w;
    }
    __syncthreads();
    #pragma unroll
    for (int i = 0; i < 4; i++) {
        int idx = tid + i * 256;
        int nl = idx >> 4, k4 = idx & 15;
        BF4 H, M;
        split2(tile[k4*4+0][nl], H.a, M.a);
        split2(tile[k4*4+1][nl], H.b, M.b);
        split2(tile[k4*4+2][nl], H.c, M.c);
        split2(tile[k4*4+3][nl], H.d, M.d);
        size_t o = ((size_t)(n0 + nl) * KDIM + k0 + k4 * 4) >> 2;
        ((BF4*)g_Wh)[o] = H;
        ((BF4*)g_Wm)[o] = M;
    }
}

// ---------------------------------------------------------------------------
// QKV GEMM via mma.sync bf16 (2-split, 3 products).
// K-chunk 32, 3-stage cp.async pipeline, one sync per chunk, 2 CTAs/SM.
// ---------------------------------------------------------------------------
#define SMEM_BUF   32768
#define SMEM_TOTAL (3*SMEM_BUF)
#define NCHUNK     32

__device__ __forceinline__ void load_chunk(u32 base, int tid, int k0, int am0, int bn0) {
    #pragma unroll
    for (int j = 0; j < 4; j++) {
        int unit = tid + j * 256;            // 0..1023
        int row = unit >> 3, u = unit & 7;
        u32 soff = row * 128 + ((u ^ (row & 7)) << 4);
        size_t goff = (size_t)k0 + ((u & 3) * 8);
        const __nv_bfloat16* sa = (u < 4) ? g_Ah : g_Am;
        const __nv_bfloat16* sb = (u < 4) ? g_Wh : g_Wm;
        cp16(base + soff,         sa + (size_t)(am0 + row) * KDIM + goff);
        cp16(base + 16384 + soff, sb + (size_t)(bn0 + row) * KDIM + goff);
    }
}

__global__ void __launch_bounds__(256, 2) qkv_mma(const float* __restrict__ bias) {
    extern __shared__ char smem[];
    const u32 sb = su32(smem);
    const int tid = threadIdx.x;
    const int wid = tid >> 5, lane = tid & 31;
    const int bn = blockIdx.x, bm = blockIdx.y;
    const int am0 = bm * 128, bn0 = bn * 128;
    const int wm = wid >> 2;
    const int wn = wid & 3;

    float acc[4][4][4];
    #pragma unroll
    for (int i = 0; i < 4; i++)
        #pragma unroll
        for (int j = 0; j < 4; j++)
            #pragma unroll
            for (int c = 0; c < 4; c++) acc[i][j][c] = 0.0f;

    const int lrow = (lane & 7) + 8 * ((lane >> 3) & 1);
    const int lu   = lane >> 4;

    load_chunk(sb, tid, 0, am0, bn0);
    cp_commit();
    load_chunk(sb + SMEM_BUF, tid, 32, am0, bn0);
    cp_commit();

    for (int t = 0; t < NCHUNK; t++) {
        if (t < NCHUNK - 2) cp_wait1(); else cp_wait0();
        __syncthreads();

        const u32 Abuf = sb + (t % 3) * SMEM_BUF;
        const u32 Bbuf = Abuf + 16384;

        #pragma unroll
        for (int kk = 0; kk < 2; kk++) {
            const int uh = 2 * kk + lu;        // hi units 0..3
            const int um = 4 + 2 * kk + lu;    // mid units 4..7
            u32 ah[4][4], am[4][4], bh[2][4], bmf[2][4];
            #pragma unroll
            for (int mt = 0; mt < 4; mt++) {
                int row = wm * 64 + mt * 16 + lrow;
                u32 rbase = row * 128;
                ldsm4(ah[mt], Abuf + rbase + ((uh ^ (row & 7)) << 4));
                ldsm4(am[mt], Abuf + rbase + ((um ^ (row & 7)) << 4));
            }
            #pragma unroll
            for (int ng = 0; ng < 2; ng++) {
                int row = wn * 32 + ng * 16 + lrow;
                u32 rbase = row * 128;
                ldsm4(bh[ng],  Bbuf + rbase + ((uh ^ (row & 7)) << 4));
                ldsm4(bmf[ng], Bbuf + rbase + ((um ^ (row & 7)) << 4));
            }
            #pragma unroll
            for (int mt = 0; mt < 4; mt++) {
                #pragma unroll
                for (int nt = 0; nt < 4; nt++) {
                    const int ng = nt >> 1, sel = nt & 1;
                    mma16816(acc[mt][nt], ah[mt], bh[ng][sel],  bh[ng][sel + 2]);
                    mma16816(acc[mt][nt], ah[mt], bmf[ng][sel], bmf[ng][sel + 2]);
                    mma16816(acc[mt][nt], am[mt], bh[ng][sel],  bh[ng][sel + 2]);
                }
            }
        }

        if (t + 2 < NCHUNK) {
            load_chunk(sb + ((t + 2) % 3) * SMEM_BUF, tid, (t + 2) * 32, am0, bn0);
            cp_commit();
        }
    }

    // --- epilogue: bias + split to bf16 hi/mid + scatter ---
    const int bb = bm >> 3, ss0 = (bm & 7) * 128;
    const int qr = lane >> 2, qc = (lane & 3) * 2;
    #pragma unroll
    for (int nt = 0; nt < 4; nt++) {
        const int coloc = wn * 32 + nt * 8 + qc;
        const int hf = coloc >> 6;
        const int cb = bn * 2 + hf;
        const int head = cb / 3;
        const int tt = cb - head * 3;
        __nv_bfloat16* dh = (tt == 0) ? g_Qh : (tt == 1) ? g_Kh : g_Vh;
        __nv_bfloat16* dm = (tt == 0) ? g_Qm : (tt == 1) ? g_Km : g_Vm;
        const int c64 = coloc & 63;
        const float2 bv = *(const float2*)&bias[bn * 128 + coloc];
        #pragma unroll
        for (int mt = 0; mt < 4; mt++) {
            #pragma unroll
            for (int half = 0; half < 2; half++) {
                const int mloc = wm * 64 + mt * 16 + qr + half * 8;
                float vx = acc[mt][nt][half * 2 + 0] + bv.x;
                float vy = acc[mt][nt][half * 2 + 1] + bv.y;
                __nv_bfloat162 H, M;
                split2(vx, H.x, M.x);
                split2(vy, H.y, M.y);
                size_t e = ((size_t)(bb * NHEAD + head) * 1024 + ss0 + mloc) * 64 + c64;
                *(__nv_bfloat162*)&dh[e] = H;
                *(__nv_bfloat162*)&dm[e] = M;
            }
        }
    }
}

// ---------------------------------------------------------------------------
// Fused attention via mma.sync bf16, flash-style online softmax.
// CTA = 64 q-rows (4 warps x m16), 128 threads; 3 CTAs/SM.
// smem: mask 4K | buf0 32K | buf1 32K = 68K. Q hi/mid staged through buf1
// (read into register A-frags before buf1's first KV load is issued).
// ---------------------------------------------------------------------------
#define AT_MASK  0
#define AT_BUF0  4096
#define AT_BUF1  (4096 + 32768)
#define AT_SMEM  (4096 + 2*32768)    // 69632

__device__ __forceinline__ void at_load_kv(u32 st, int tid, size_t base, int kt) {
    size_t goff0 = base + (size_t)kt * 64 * 64;
    #pragma unroll
    for (int r = 0; r < 4; r++) {
        int unit = tid + r * 128;
        int row = unit >> 3, u = unit & 7;
        u32 soff = row * 128 + ((u ^ (row & 7)) << 4);
        size_t g = goff0 + row * 64 + u * 8;
        cp16(st + soff,         g_Kh + g);
        cp16(st + 8192 + soff,  g_Km + g);
        cp16(st + 16384 + soff, g_Vh + g);
        cp16(st + 24576 + soff, g_Vm + g);
    }
}

__global__ void __launch_bounds__(128, 3) attn_mma(
    const int* __restrict__ mask, float* __restrict__ out)
{
    extern __shared__ char smem[];
    const u32 sb = su32(smem);
    const int tid = threadIdx.x;
    const int wid = tid >> 5, lane = tid & 31;
    const int qt = blockIdx.x & 15;
    const int bh = blockIdx.x >> 4;
    const int bb = bh >> 4;
    const int hh = bh & 15;
    const size_t base = (size_t)bh * (SEQ * HDIM);

    const int lrow = (lane & 7) + 8 * ((lane >> 3) & 1);
    const int lu   = lane >> 4;
    const int qr   = lane >> 2;
    const int qc2  = (lane & 3) * 2;

    // prologue group 0: mask + Q (into buf1) + KV tile 0 (into buf0)
    #pragma unroll
    for (int r = 0; r < 2; r++)
        cp16(sb + AT_MASK + (tid + r * 128) * 16, mask + bb * SEQ + (tid + r * 128) * 4);
    {
        size_t q0 = base + (size_t)qt * 64 * 64;
        #pragma unroll
        for (int r = 0; r < 4; r++) {
            int unit = tid + r * 128;
            int row = unit >> 3, u = unit & 7;
            u32 soff = row * 128 + ((u ^ (row & 7)) << 4);
            size_t g = q0 + row * 64 + u * 8;
            cp16(sb + AT_BUF1 + soff,        g_Qh + g);
            cp16(sb + AT_BUF1 + 8192 + soff, g_Qm + g);
        }
    }
    at_load_kv(sb + AT_BUF0, tid, base, 0);
    cp_commit();
    cp_wait0();
    __syncthreads();

    // preload Q A-frags from buf1, then release buf1 for KV tile 1
    u32 qha[4][4], qma[4][4];
    #pragma unroll
    for (int kk = 0; kk < 4; kk++) {
        int row = wid * 16 + lrow;
        int u = 2 * kk + lu;
        u32 off = row * 128 + ((u ^ (row & 7)) << 4);
        ldsm4(qha[kk], sb + AT_BUF1 + off);
        ldsm4(qma[kk], sb + AT_BUF1 + 8192 + off);
    }
    __syncthreads();
    at_load_kv(sb + AT_BUF1, tid, base, 1);
    cp_commit();

    float mrun[2] = { -1e30f, -1e30f };
    float lrun[2] = { 0.0f, 0.0f };
    float oacc[8][4];
    #pragma unroll
    for (int n = 0; n < 8; n++)
        #pragma unroll
        for (int c = 0; c < 4; c++) oacc[n][c] = 0.0f;

    for (int kt = 0; kt < 16; kt++) {
        const u32 st = sb + ((kt & 1) ? AT_BUF1 : AT_BUF0);

        // --- S = Q K^T ---
        float p[8][4];
        #pragma unroll
        for (int s = 0; s < 8; s++)
            #pragma unroll
            for (int c = 0; c < 4; c++) p[s][c] = 0.0f;

        #pragma unroll
        for (int kk = 0; kk < 4; kk++) {
            const int uu = 2 * kk + lu;
            u32 kh[4][4], km[4][4];
            #pragma unroll
            for (int kg = 0; kg < 4; kg++) {
                int row = kg * 16 + lrow;
                u32 off = row * 128 + ((uu ^ (row & 7)) << 4);
                ldsm4(kh[kg], st + off);
                ldsm4(km[kg], st + 8192 + off);
            }
            #pragma unroll
            for (int s = 0; s < 8; s++) {
                const int kg = s >> 1, hf = s & 1;
                mma16816(p[s], qha[kk], kh[kg][hf], kh[kg][hf + 2]);
                mma16816(p[s], qha[kk], km[kg][hf], km[kg][hf + 2]);
                mma16816(p[s], qma[kk], kh[kg][hf], kh[kg][hf + 2]);
            }
        }

        // --- mask + scale ---
        #pragma unroll
        for (int s = 0; s < 8; s++) {
            int2 mv = *(const int2*)(smem + AT_MASK + (size_t)(kt * 64 + s * 8 + qc2) * 4);
            p[s][0] = mv.x ? -10000.0f : p[s][0] * 8.0f;
            p[s][1] = mv.y ? -10000.0f : p[s][1] * 8.0f;
            p[s][2] = mv.x ? -10000.0f : p[s][2] * 8.0f;
            p[s][3] = mv.y ? -10000.0f : p[s][3] * 8.0f;
        }

        // --- online softmax ---
        #pragma unroll
        for (int h = 0; h < 2; h++) {
            float tm = -1e30f;
            #pragma unroll
            for (int s = 0; s < 8; s++)
                tm = fmaxf(tm, fmaxf(p[s][2*h], p[s][2*h + 1]));
            tm = fmaxf(tm, __shfl_xor_sync(0xffffffffu, tm, 1));
            tm = fmaxf(tm, __shfl_xor_sync(0xffffffffu, tm, 2));
            float mnew = fmaxf(mrun[h], tm);
            float ts = 0.0f;
            #pragma unroll
            for (int s = 0; s < 8; s++) {
                p[s][2*h]     = __expf(p[s][2*h]     - mnew);
                p[s][2*h + 1] = __expf(p[s][2*h + 1] - mnew);
                ts += p[s][2*h] + p[s][2*h + 1];
            }
            ts += __shfl_xor_sync(0xffffffffu, ts, 1);
            ts += __shfl_xor_sync(0xffffffffu, ts, 2);
            float alpha = __expf(mrun[h] - mnew);
            lrun[h] = lrun[h] * alpha + ts;
            mrun[h] = mnew;
            #pragma unroll
            for (int n = 0; n < 8; n++) {
                oacc[n][2*h]     *= alpha;
                oacc[n][2*h + 1] *= alpha;
            }
        }

        // --- O += P V ---
        #pragma unroll
        for (int kg = 0; kg < 4; kg++) {
            u32 pha[4], pma[4];
            pha[0] = cvtbf2(p[2*kg][0],     p[2*kg][1]);
            pha[1] = cvtbf2(p[2*kg][2],     p[2*kg][3]);
            pha[2] = cvtbf2(p[2*kg + 1][0], p[2*kg + 1][1]);
            pha[3] = cvtbf2(p[2*kg + 1][2], p[2*kg + 1][3]);
            pma[0] = resbf2(p[2*kg][0],     p[2*kg][1],     pha[0]);
            pma[1] = resbf2(p[2*kg][2],     p[2*kg][3],     pha[1]);
            pma[2] = resbf2(p[2*kg + 1][0], p[2*kg + 1][1], pha[2]);
            pma[3] = resbf2(p[2*kg + 1][2], p[2*kg + 1][3], pha[3]);

            u32 vh[4][4], vm[4][4];
            #pragma unroll
            for (int ng = 0; ng < 4; ng++) {
                int row = kg * 16 + lrow;
                int u = 2 * ng + lu;
                u32 off = row * 128 + ((u ^ (row & 7)) << 4);
                ldsm4t(vh[ng], st + 16384 + off);
                ldsm4t(vm[ng], st + 24576 + off);
            }
            #pragma unroll
            for (int n8 = 0; n8 < 8; n8++) {
                const int ng = n8 >> 1, hf = n8 & 1;
                mma16816(oacc[n8], pha, vh[ng][2*hf], vh[ng][2*hf + 1]);
                mma16816(oacc[n8], pha, vm[ng][2*hf], vm[ng][2*hf + 1]);
                mma16816(oacc[n8], pma, vh[ng][2*hf], vh[ng][2*hf + 1]);
            }
        }

        __syncthreads();
        if (kt + 2 < 16) {
            at_load_kv(sb + ((kt & 1) ? AT_BUF1 : AT_BUF0), tid, base, kt + 2);
            cp_commit();
        }
        if (kt + 1 < 16) {
            if (kt + 2 < 16) cp_wait1(); else cp_wait0();
            __syncthreads();
        }
    }

    // --- epilogue ---
    #pragma unroll
    for (int h = 0; h < 2; h++) {
        float inv = 1.0f / lrun[h];
        int qrow = qt * 64 + wid * 16 + qr + h * 8;
        float* drow = out + ((size_t)(bb * SEQ + qrow)) * HID + hh * 64;
        #pragma unroll
        for (int n8 = 0; n8 < 8; n8++) {
            float2 v;
            v.x = oacc[n8][2*h]     * inv;
            v.y = oacc[n8][2*h + 1] * inv;
            *(float2*)&drow[n8 * 8 + qc2] = v;
        }
    }
}

extern "C" void kernel_launch(void* const* d_in, const int* in_sizes, int n_in,
                              void* d_out, int out_size)
{
    const float* hidden = (const float*)d_in[0];
    const int*   mask   = (const int*)  d_in[1];
    const float* w_qkv  = (const float*)d_in[2];
    const float* b_qkv  = (const float*)d_in[3];
    float* out = (float*)d_out;

    cudaFuncSetAttribute(qkv_mma, cudaFuncAttributeMaxDynamicSharedMemorySize, SMEM_TOTAL);
    cudaFuncSetAttribute(attn_mma, cudaFuncAttributeMaxDynamicSharedMemorySize, AT_SMEM);

    split_hidden<<<MROWS * KDIM / 4 / 256, 256>>>(hidden);
    split_w<<<dim3(N3 / 64, KDIM / 64), 256>>>(w_qkv);
    qkv_mma<<<dim3(N3 / 128, MROWS / 128), 256, SMEM_TOTAL>>>(b_qkv);
    attn_mma<<<BATCH * NHEAD * (SEQ / 64), 128, AT_SMEM>>>(mask, out);
}

// round 16
// speedup vs baseline: 1.6206x; 1.6206x over previous
#include <cuda_runtime.h>
#include <cuda_bf16.h>
#include <cstdint>
#include <math.h>

#define BATCH 8
#define SEQ   1024
#define HID   1024
#define NHEAD 16
#define HDIM  64
#define N3    3072
#define MROWS 8192
#define KDIM  1024

typedef unsigned long long u64;
typedef unsigned int u32;

// ---------------------------------------------------------------------------
// Scratch globals: bf16 2-way splits everywhere
// ---------------------------------------------------------------------------
__device__ __align__(16) __nv_bfloat16 g_Ah[MROWS*KDIM];
__device__ __align__(16) __nv_bfloat16 g_Am[MROWS*KDIM];
__device__ __align__(16) __nv_bfloat16 g_Wh[N3*KDIM];
__device__ __align__(16) __nv_bfloat16 g_Wm[N3*KDIM];

__device__ __align__(16) __nv_bfloat16 g_Qh[BATCH*NHEAD*SEQ*HDIM];
__device__ __align__(16) __nv_bfloat16 g_Qm[BATCH*NHEAD*SEQ*HDIM];
__device__ __align__(16) __nv_bfloat16 g_Kh[BATCH*NHEAD*SEQ*HDIM];
__device__ __align__(16) __nv_bfloat16 g_Km[BATCH*NHEAD*SEQ*HDIM];
__device__ __align__(16) __nv_bfloat16 g_Vh[BATCH*NHEAD*SEQ*HDIM];
__device__ __align__(16) __nv_bfloat16 g_Vm[BATCH*NHEAD*SEQ*HDIM];

// compacted (unmasked keys only), zero-padded to 64-row tiles
__device__ __align__(16) __nv_bfloat16 g_Kch[BATCH*NHEAD*SEQ*HDIM];
__device__ __align__(16) __nv_bfloat16 g_Kcm[BATCH*NHEAD*SEQ*HDIM];
__device__ __align__(16) __nv_bfloat16 g_Vch[BATCH*NHEAD*SEQ*HDIM];
__device__ __align__(16) __nv_bfloat16 g_Vcm[BATCH*NHEAD*SEQ*HDIM];

__device__ int g_cnt[BATCH];
__device__ int g_sidx[BATCH*SEQ];

// ---------------------------------------------------------------------------
// helpers
// ---------------------------------------------------------------------------
__device__ __forceinline__ u32 su32(const void* p) {
    u32 a;
    asm("{ .reg .u64 t; cvta.to.shared.u64 t, %1; cvt.u32.u64 %0, t; }" : "=r"(a) : "l"(p));
    return a;
}
__device__ __forceinline__ void cp16(u32 sm, const void* g) {
    asm volatile("cp.async.cg.shared.global [%0], [%1], 16;" :: "r"(sm), "l"(g));
}
__device__ __forceinline__ void cp_commit() {
    asm volatile("cp.async.commit_group;" ::: "memory");
}
__device__ __forceinline__ void cp_wait1() {
    asm volatile("cp.async.wait_group 1;" ::: "memory");
}
__device__ __forceinline__ void cp_wait0() {
    asm volatile("cp.async.wait_group 0;" ::: "memory");
}
__device__ __forceinline__ void ldsm4(u32* r, u32 addr) {
    asm volatile("ldmatrix.sync.aligned.m8n8.x4.shared.b16 {%0,%1,%2,%3}, [%4];"
                 : "=r"(r[0]), "=r"(r[1]), "=r"(r[2]), "=r"(r[3]) : "r"(addr));
}
__device__ __forceinline__ void ldsm4t(u32* r, u32 addr) {
    asm volatile("ldmatrix.sync.aligned.m8n8.x4.trans.shared.b16 {%0,%1,%2,%3}, [%4];"
                 : "=r"(r[0]), "=r"(r[1]), "=r"(r[2]), "=r"(r[3]) : "r"(addr));
}
__device__ __forceinline__ void mma16816(float* d, const u32* a, u32 b0, u32 b1) {
    asm volatile(
        "mma.sync.aligned.m16n8k16.row.col.f32.bf16.bf16.f32 "
        "{%0,%1,%2,%3}, {%4,%5,%6,%7}, {%8,%9}, {%0,%1,%2,%3};"
        : "+f"(d[0]), "+f"(d[1]), "+f"(d[2]), "+f"(d[3])
        : "r"(a[0]), "r"(a[1]), "r"(a[2]), "r"(a[3]), "r"(b0), "r"(b1));
}
__device__ __forceinline__ u32 cvtbf2(float lo, float hi) {
    u32 r; asm("cvt.rn.bf16x2.f32 %0, %1, %2;" : "=r"(r) : "f"(hi), "f"(lo)); return r;
}
__device__ __forceinline__ u32 resbf2(float lo, float hi, u32 h) {
    __nv_bfloat162 hb = *reinterpret_cast<__nv_bfloat162*>(&h);
    float2 hf = __bfloat1622float2(hb);
    return cvtbf2(lo - hf.x, hi - hf.y);
}

// ---------------------------------------------------------------------------
// split kernels: fp32 -> bf16 hi/mid
// ---------------------------------------------------------------------------
struct __align__(8) BF4 { __nv_bfloat16 a, b, c, d; };

__device__ __forceinline__ void split2(float x, __nv_bfloat16& h, __nv_bfloat16& m) {
    h = __float2bfloat16(x);
    m = __float2bfloat16(x - __bfloat162float(h));
}

__global__ void __launch_bounds__(256) split_hidden(const float* __restrict__ x) {
    size_t i = (size_t)blockIdx.x * 256 + threadIdx.x;
    float4 v = ((const float4*)x)[i];
    BF4 H, M;
    split2(v.x, H.a, M.a);
    split2(v.y, H.b, M.b);
    split2(v.z, H.c, M.c);
    split2(v.w, H.d, M.d);
    ((BF4*)g_Ah)[i] = H;
    ((BF4*)g_Am)[i] = M;
}

__global__ void __launch_bounds__(256) split_w(const float* __restrict__ w) {
    __shared__ float tile[64][65];
    const int n0 = blockIdx.x * 64, k0 = blockIdx.y * 64;
    const int tid = threadIdx.x;
    #pragma unroll
    for (int i = 0; i < 4; i++) {
        int idx = tid + i * 256;
        int r = idx >> 4, c4 = idx & 15;
        float4 v = *(const float4*)&w[(size_t)(k0 + r) * N3 + n0 + c4 * 4];
        tile[r][c4*4+0] = v.x; tile[r][c4*4+1] = v.y;
        tile[r][c4*4+2] = v.z; tile[r][c4*4+3] = v.w;
    }
    __syncthreads();
    #pragma unroll
    for (int i = 0; i < 4; i++) {
        int idx = tid + i * 256;
        int nl = idx >> 4, k4 = idx & 15;
        BF4 H, M;
        split2(tile[k4*4+0][nl], H.a, M.a);
        split2(tile[k4*4+1][nl], H.b, M.b);
        split2(tile[k4*4+2][nl], H.c, M.c);
        split2(tile[k4*4+3][nl], H.d, M.d);
        size_t o = ((size_t)(n0 + nl) * KDIM + k0 + k4 * 4) >> 2;
        ((BF4*)g_Wh)[o] = H;
        ((BF4*)g_Wm)[o] = M;
    }
}

// ---------------------------------------------------------------------------
// mask scan: per batch, list of unmasked key indices + count
// (reference: masked where mask != 0; kept keys are mask == 0)
// ---------------------------------------------------------------------------
__global__ void __launch_bounds__(1024) scan_mask(const int* __restrict__ mask) {
    __shared__ int sc[1024];
    const int b = blockIdx.x, t = threadIdx.x;
    const int keep = (mask[b * SEQ + t] == 0) ? 1 : 0;
    sc[t] = keep;
    __syncthreads();
    for (int off = 1; off < 1024; off <<= 1) {
        int v = sc[t];
        if (t >= off) v += sc[t - off];
        __syncthreads();
        sc[t] = v;
        __syncthreads();
    }
    if (keep) g_sidx[b * SEQ + sc[t] - 1] = t;
    if (t == 1023) g_cnt[b] = sc[1023];
}

// ---------------------------------------------------------------------------
// compact K/V (hi+mid) per (b,h): gather unmasked rows, zero-pad to 64
// ---------------------------------------------------------------------------
__global__ void __launch_bounds__(256) compact_kv() {
    const int bh = blockIdx.x;
    const int b = bh >> 4;
    const int cnt = g_cnt[b];
    const int padded = (cnt + 63) & ~63;
    const int t = threadIdx.x;
    const int u = t & 7, arr = (t >> 3) & 3, r0 = t >> 5;
    const __nv_bfloat16* src = (arr == 0) ? g_Kh : (arr == 1) ? g_Km : (arr == 2) ? g_Vh : g_Vm;
    __nv_bfloat16* dst = (arr == 0) ? g_Kch : (arr == 1) ? g_Kcm : (arr == 2) ? g_Vch : g_Vcm;
    const size_t basebh = (size_t)bh * (SEQ * HDIM);
    for (int r = r0; r < padded; r += 8) {
        uint4 v = make_uint4(0u, 0u, 0u, 0u);
        if (r < cnt) {
            int s = g_sidx[b * SEQ + r];
            v = *(const uint4*)(src + basebh + (size_t)s * 64 + u * 8);
        }
        *(uint4*)(dst + basebh + (size_t)r * 64 + u * 8) = v;
    }
}

// ---------------------------------------------------------------------------
// QKV GEMM via mma.sync bf16 (2-split, 3 products).  [R13 config]
// K-chunk 32; row = [hi 64B | mid 64B], swizzle u^(row&7). 2-stage, 2 CTA/SM.
// ---------------------------------------------------------------------------
#define SMEM_BUF   32768
#define SMEM_TOTAL (2*SMEM_BUF)
#define NCHUNK     32

__device__ __forceinline__ void load_chunk(u32 base, int tid, int k0, int am0, int bn0) {
    #pragma unroll
    for (int j = 0; j < 4; j++) {
        int unit = tid + j * 256;
        int row = unit >> 3, u = unit & 7;
        u32 soff = row * 128 + ((u ^ (row & 7)) << 4);
        size_t goff = (size_t)k0 + ((u & 3) * 8);
        const __nv_bfloat16* sa = (u < 4) ? g_Ah : g_Am;
        const __nv_bfloat16* sb = (u < 4) ? g_Wh : g_Wm;
        cp16(base + soff,         sa + (size_t)(am0 + row) * KDIM + goff);
        cp16(base + 16384 + soff, sb + (size_t)(bn0 + row) * KDIM + goff);
    }
}

__global__ void __launch_bounds__(256, 2) qkv_mma(const float* __restrict__ bias) {
    extern __shared__ char smem[];
    const u32 sb = su32(smem);
    const int tid = threadIdx.x;
    const int wid = tid >> 5, lane = tid & 31;
    const int bn = blockIdx.x, bm = blockIdx.y;
    const int am0 = bm * 128, bn0 = bn * 128;
    const int wm = wid >> 2;
    const int wn = wid & 3;

    float acc[4][4][4];
    #pragma unroll
    for (int i = 0; i < 4; i++)
        #pragma unroll
        for (int j = 0; j < 4; j++)
            #pragma unroll
            for (int c = 0; c < 4; c++) acc[i][j][c] = 0.0f;

    const int lrow = (lane & 7) + 8 * ((lane >> 3) & 1);
    const int lu   = lane >> 4;

    load_chunk(sb, tid, 0, am0, bn0);
    cp_commit();

    for (int t = 0; t < NCHUNK; t++) {
        if (t + 1 < NCHUNK) {
            load_chunk(sb + ((t + 1) & 1) * SMEM_BUF, tid, (t + 1) * 32, am0, bn0);
            cp_commit();
            cp_wait1();
        } else {
            cp_wait0();
        }
        __syncthreads();

        const u32 Abuf = sb + (t & 1) * SMEM_BUF;
        const u32 Bbuf = Abuf + 16384;

        #pragma unroll
        for (int kk = 0; kk < 2; kk++) {
            const int uh = 2 * kk + lu;
            const int um = 4 + 2 * kk + lu;
            u32 ah[4][4], am[4][4], bh[2][4], bmf[2][4];
            #pragma unroll
            for (int mt = 0; mt < 4; mt++) {
                int row = wm * 64 + mt * 16 + lrow;
                u32 rbase = row * 128;
                ldsm4(ah[mt], Abuf + rbase + ((uh ^ (row & 7)) << 4));
                ldsm4(am[mt], Abuf + rbase + ((um ^ (row & 7)) << 4));
            }
            #pragma unroll
            for (int ng = 0; ng < 2; ng++) {
                int row = wn * 32 + ng * 16 + lrow;
                u32 rbase = row * 128;
                ldsm4(bh[ng],  Bbuf + rbase + ((uh ^ (row & 7)) << 4));
                ldsm4(bmf[ng], Bbuf + rbase + ((um ^ (row & 7)) << 4));
            }
            #pragma unroll
            for (int mt = 0; mt < 4; mt++) {
                #pragma unroll
                for (int nt = 0; nt < 4; nt++) {
                    const int ng = nt >> 1, sel = nt & 1;
                    mma16816(acc[mt][nt], ah[mt], bh[ng][sel],  bh[ng][sel + 2]);
                    mma16816(acc[mt][nt], ah[mt], bmf[ng][sel], bmf[ng][sel + 2]);
                    mma16816(acc[mt][nt], am[mt], bh[ng][sel],  bh[ng][sel + 2]);
                }
            }
        }
        __syncthreads();
    }

    // --- epilogue: bias + split to bf16 hi/mid + scatter ---
    const int bb = bm >> 3, ss0 = (bm & 7) * 128;
    const int qr = lane >> 2, qc = (lane & 3) * 2;
    #pragma unroll
    for (int nt = 0; nt < 4; nt++) {
        const int coloc = wn * 32 + nt * 8 + qc;
        const int hf = coloc >> 6;
        const int cb = bn * 2 + hf;
        const int head = cb / 3;
        const int tt = cb - head * 3;
        __nv_bfloat16* dh = (tt == 0) ? g_Qh : (tt == 1) ? g_Kh : g_Vh;
        __nv_bfloat16* dm = (tt == 0) ? g_Qm : (tt == 1) ? g_Km : g_Vm;
        const int c64 = coloc & 63;
        const float2 bv = *(const float2*)&bias[bn * 128 + coloc];
        #pragma unroll
        for (int mt = 0; mt < 4; mt++) {
            #pragma unroll
            for (int half = 0; half < 2; half++) {
                const int mloc = wm * 64 + mt * 16 + qr + half * 8;
                float vx = acc[mt][nt][half * 2 + 0] + bv.x;
                float vy = acc[mt][nt][half * 2 + 1] + bv.y;
                __nv_bfloat162 H, M;
                split2(vx, H.x, M.x);
                split2(vy, H.y, M.y);
                size_t e = ((size_t)(bb * NHEAD + head) * 1024 + ss0 + mloc) * 64 + c64;
                *(__nv_bfloat162*)&dh[e] = H;
                *(__nv_bfloat162*)&dm[e] = M;
            }
        }
    }
}

// ---------------------------------------------------------------------------
// Fused attention via mma.sync bf16 over COMPACTED keys.
// CTA = 64 q-rows (4 warps x m16), 128 threads. [R13 structure]
// smem: QH 8K | QM 8K | 2 x 32K KV stages = 80K.
// ---------------------------------------------------------------------------
#define AT_QH    0
#define AT_QM    8192
#define AT_KV    16384
#define AT_STAGE 32768
#define AT_SMEM  (16384 + 2*32768)   // 81920

__device__ __forceinline__ void at_load_kv(u32 sb, int stg, int tid, size_t base, int kt) {
    u32 st = sb + AT_KV + stg * AT_STAGE;
    size_t goff0 = base + (size_t)kt * 64 * 64;
    #pragma unroll
    for (int r = 0; r < 4; r++) {
        int unit = tid + r * 128;
        int row = unit >> 3, u = unit & 7;
        u32 soff = row * 128 + ((u ^ (row & 7)) << 4);
        size_t g = goff0 + row * 64 + u * 8;
        cp16(st + soff,         g_Kch + g);
        cp16(st + 8192 + soff,  g_Kcm + g);
        cp16(st + 16384 + soff, g_Vch + g);
        cp16(st + 24576 + soff, g_Vcm + g);
    }
}

__global__ void __launch_bounds__(128) attn_mma(float* __restrict__ out) {
    extern __shared__ char smem[];
    const u32 sb = su32(smem);
    const int tid = threadIdx.x;
    const int wid = tid >> 5, lane = tid & 31;
    const int qt = blockIdx.x & 15;
    const int bh = blockIdx.x >> 4;
    const int bb = bh >> 4;
    const int hh = bh & 15;
    const size_t base = (size_t)bh * (SEQ * HDIM);

    const int cnt = g_cnt[bb];
    const int ntiles = (cnt + 63) >> 6;

    const int lrow = (lane & 7) + 8 * ((lane >> 3) & 1);
    const int lu   = lane >> 4;
    const int qr   = lane >> 2;
    const int qc2  = (lane & 3) * 2;

    // prologue: Q tile + KV tile 0 | KV tile 1
    {
        size_t q0 = base + (size_t)qt * 64 * 64;
        #pragma unroll
        for (int r = 0; r < 4; r++) {
            int unit = tid + r * 128;
            int row = unit >> 3, u = unit & 7;
            u32 soff = row * 128 + ((u ^ (row & 7)) << 4);
            size_t g = q0 + row * 64 + u * 8;
            cp16(sb + AT_QH + soff, g_Qh + g);
            cp16(sb + AT_QM + soff, g_Qm + g);
        }
    }
    at_load_kv(sb, 0, tid, base, 0);
    cp_commit();
    if (ntiles > 1) at_load_kv(sb, 1, tid, base, 1);
    cp_commit();
    cp_wait1();
    __syncthreads();

    // preload Q A-frags
    u32 qha[4][4], qma[4][4];
    #pragma unroll
    for (int kk = 0; kk < 4; kk++) {
        int row = wid * 16 + lrow;
        int u = 2 * kk + lu;
        u32 off = row * 128 + ((u ^ (row & 7)) << 4);
        ldsm4(qha[kk], sb + AT_QH + off);
        ldsm4(qma[kk], sb + AT_QM + off);
    }

    float mrun[2] = { -1e30f, -1e30f };
    float lrun[2] = { 0.0f, 0.0f };
    float oacc[8][4];
    #pragma unroll
    for (int n = 0; n < 8; n++)
        #pragma unroll
        for (int c = 0; c < 4; c++) oacc[n][c] = 0.0f;

    for (int kt = 0; kt < ntiles; kt++) {
        const u32 st = sb + AT_KV + (kt & 1) * AT_STAGE;

        // --- S = Q K^T ---
        float p[8][4];
        #pragma unroll
        for (int s = 0; s < 8; s++)
            #pragma unroll
            for (int c = 0; c < 4; c++) p[s][c] = 0.0f;

        #pragma unroll
        for (int kk = 0; kk < 4; kk++) {
            const int uu = 2 * kk + lu;
            u32 kh[4][4], km[4][4];
            #pragma unroll
            for (int kg = 0; kg < 4; kg++) {
                int row = kg * 16 + lrow;
                u32 off = row * 128 + ((uu ^ (row & 7)) << 4);
                ldsm4(kh[kg], st + off);
                ldsm4(km[kg], st + 8192 + off);
            }
            #pragma unroll
            for (int s = 0; s < 8; s++) {
                const int kg = s >> 1, hf = s & 1;
                mma16816(p[s], qha[kk], kh[kg][hf], kh[kg][hf + 2]);
                mma16816(p[s], qha[kk], km[kg][hf], km[kg][hf + 2]);
                mma16816(p[s], qma[kk], kh[kg][hf], kh[kg][hf + 2]);
            }
        }

        // --- scale; pad columns (>= cnt) -> -10000 (exp underflows to 0) ---
        #pragma unroll
        for (int s = 0; s < 8; s++) {
            const int c = kt * 64 + s * 8 + qc2;
            const bool v0 = (c < cnt), v1 = (c + 1 < cnt);
            p[s][0] = v0 ? p[s][0] * 8.0f : -10000.0f;
            p[s][1] = v1 ? p[s][1] * 8.0f : -10000.0f;
            p[s][2] = v0 ? p[s][2] * 8.0f : -10000.0f;
            p[s][3] = v1 ? p[s][3] * 8.0f : -10000.0f;
        }

        // --- online softmax ---
        #pragma unroll
        for (int h = 0; h < 2; h++) {
            float tm = -1e30f;
            #pragma unroll
            for (int s = 0; s < 8; s++)
                tm = fmaxf(tm, fmaxf(p[s][2*h], p[s][2*h + 1]));
            tm = fmaxf(tm, __shfl_xor_sync(0xffffffffu, tm, 1));
            tm = fmaxf(tm, __shfl_xor_sync(0xffffffffu, tm, 2));
            float mnew = fmaxf(mrun[h], tm);
            float ts = 0.0f;
            #pragma unroll
            for (int s = 0; s < 8; s++) {
                p[s][2*h]     = __expf(p[s][2*h]     - mnew);
                p[s][2*h + 1] = __expf(p[s][2*h + 1] - mnew);
                ts += p[s][2*h] + p[s][2*h + 1];
            }
            ts += __shfl_xor_sync(0xffffffffu, ts, 1);
            ts += __shfl_xor_sync(0xffffffffu, ts, 2);
            float alpha = __expf(mrun[h] - mnew);
            lrun[h] = lrun[h] * alpha + ts;
            mrun[h] = mnew;
            #pragma unroll
            for (int n = 0; n < 8; n++) {
                oacc[n][2*h]     *= alpha;
                oacc[n][2*h + 1] *= alpha;
            }
        }

        // --- O += P V ---
        #pragma unroll
        for (int kg = 0; kg < 4; kg++) {
            u32 pha[4], pma[4];
            pha[0] = cvtbf2(p[2*kg][0],     p[2*kg][1]);
            pha[1] = cvtbf2(p[2*kg][2],     p[2*kg][3]);
            pha[2] = cvtbf2(p[2*kg + 1][0], p[2*kg + 1][1]);
            pha[3] = cvtbf2(p[2*kg + 1][2], p[2*kg + 1][3]);
            pma[0] = resbf2(p[2*kg][0],     p[2*kg][1],     pha[0]);
            pma[1] = resbf2(p[2*kg][2],     p[2*kg][3],     pha[1]);
            pma[2] = resbf2(p[2*kg + 1][0], p[2*kg + 1][1], pha[2]);
            pma[3] = resbf2(p[2*kg + 1][2], p[2*kg + 1][3], pha[3]);

            u32 vh[4][4], vm[4][4];
            #pragma unroll
            for (int ng = 0; ng < 4; ng++) {
                int row = kg * 16 + lrow;
                int u = 2 * ng + lu;
                u32 off = row * 128 + ((u ^ (row & 7)) << 4);
                ldsm4t(vh[ng], st + 16384 + off);
                ldsm4t(vm[ng], st + 24576 + off);
            }
            #pragma unroll
            for (int n8 = 0; n8 < 8; n8++) {
                const int ng = n8 >> 1, hf = n8 & 1;
                mma16816(oacc[n8], pha, vh[ng][2*hf], vh[ng][2*hf + 1]);
                mma16816(oacc[n8], pha, vm[ng][2*hf], vm[ng][2*hf + 1]);
                mma16816(oacc[n8], pma, vh[ng][2*hf], vh[ng][2*hf + 1]);
            }
        }

        __syncthreads();
        if (kt + 2 < ntiles) {
            at_load_kv(sb, kt & 1, tid, base, kt + 2);
            cp_commit();
        }
        if (kt + 1 < ntiles) {
            if (kt + 2 < ntiles) cp_wait1(); else cp_wait0();
            __syncthreads();
        }
    }

    // --- epilogue ---
    #pragma unroll
    for (int h = 0; h < 2; h++) {
        float inv = 1.0f / lrun[h];
        int qrow = qt * 64 + wid * 16 + qr + h * 8;
        float* drow = out + ((size_t)(bb * SEQ + qrow)) * HID + hh * 64;
        #pragma unroll
        for (int n8 = 0; n8 < 8; n8++) {
            float2 v;
            v.x = oacc[n8][2*h]     * inv;
            v.y = oacc[n8][2*h + 1] * inv;
            *(float2*)&drow[n8 * 8 + qc2] = v;
        }
    }
}

extern "C" void kernel_launch(void* const* d_in, const int* in_sizes, int n_in,
                              void* d_out, int out_size)
{
    const float* hidden = (const float*)d_in[0];
    const int*   mask   = (const int*)  d_in[1];
    const float* w_qkv  = (const float*)d_in[2];
    const float* b_qkv  = (const float*)d_in[3];
    float* out = (float*)d_out;

    cudaFuncSetAttribute(qkv_mma, cudaFuncAttributeMaxDynamicSharedMemorySize, SMEM_TOTAL);
    cudaFuncSetAttribute(attn_mma, cudaFuncAttributeMaxDynamicSharedMemorySize, AT_SMEM);

    split_hidden<<<MROWS * KDIM / 4 / 256, 256>>>(hidden);
    split_w<<<dim3(N3 / 64, KDIM / 64), 256>>>(w_qkv);
    scan_mask<<<BATCH, 1024>>>(mask);
    qkv_mma<<<dim3(N3 / 128, MROWS / 128), 256, SMEM_TOTAL>>>(b_qkv);
    compact_kv<<<BATCH * NHEAD, 256>>>();
    attn_mma<<<BATCH * NHEAD * (SEQ / 64), 128, AT_SMEM>>>(out);
}

// round 17
// speedup vs baseline: 2.1097x; 1.3018x over previous
#include <cuda_runtime.h>
#include <cuda_bf16.h>
#include <cstdint>
#include <math.h>

#define BATCH 8
#define SEQ   1024
#define HID   1024
#define NHEAD 16
#define HDIM  64
#define N3    3072
#define MROWS 8192
#define KDIM  1024

typedef unsigned long long u64;
typedef unsigned int u32;

// ---------------------------------------------------------------------------
// Scratch globals: bf16 2-way splits everywhere
// ---------------------------------------------------------------------------
__device__ __align__(16) __nv_bfloat16 g_Ah[MROWS*KDIM];
__device__ __align__(16) __nv_bfloat16 g_Am[MROWS*KDIM];
__device__ __align__(16) __nv_bfloat16 g_cAh[MROWS*KDIM];   // mask-compacted A rows
__device__ __align__(16) __nv_bfloat16 g_cAm[MROWS*KDIM];
__device__ __align__(16) __nv_bfloat16 g_Wh[N3*KDIM];
__device__ __align__(16) __nv_bfloat16 g_Wm[N3*KDIM];

__device__ __align__(16) __nv_bfloat16 g_Qh[BATCH*NHEAD*SEQ*HDIM];
__device__ __align__(16) __nv_bfloat16 g_Qm[BATCH*NHEAD*SEQ*HDIM];

// compacted (unmasked keys only), zero/bias-padded to tile boundary
__device__ __align__(16) __nv_bfloat16 g_Kch[BATCH*NHEAD*SEQ*HDIM];
__device__ __align__(16) __nv_bfloat16 g_Kcm[BATCH*NHEAD*SEQ*HDIM];
__device__ __align__(16) __nv_bfloat16 g_Vch[BATCH*NHEAD*SEQ*HDIM];
__device__ __align__(16) __nv_bfloat16 g_Vcm[BATCH*NHEAD*SEQ*HDIM];

__device__ int g_cnt[BATCH];
__device__ int g_sidx[BATCH*SEQ];

// ---------------------------------------------------------------------------
// helpers
// ---------------------------------------------------------------------------
__device__ __forceinline__ u32 su32(const void* p) {
    u32 a;
    asm("{ .reg .u64 t; cvta.to.shared.u64 t, %1; cvt.u32.u64 %0, t; }" : "=r"(a) : "l"(p));
    return a;
}
__device__ __forceinline__ void cp16(u32 sm, const void* g) {
    asm volatile("cp.async.cg.shared.global [%0], [%1], 16;" :: "r"(sm), "l"(g));
}
__device__ __forceinline__ void cp_commit() {
    asm volatile("cp.async.commit_group;" ::: "memory");
}
__device__ __forceinline__ void cp_wait1() {
    asm volatile("cp.async.wait_group 1;" ::: "memory");
}
__device__ __forceinline__ void cp_wait0() {
    asm volatile("cp.async.wait_group 0;" ::: "memory");
}
__device__ __forceinline__ void ldsm4(u32* r, u32 addr) {
    asm volatile("ldmatrix.sync.aligned.m8n8.x4.shared.b16 {%0,%1,%2,%3}, [%4];"
                 : "=r"(r[0]), "=r"(r[1]), "=r"(r[2]), "=r"(r[3]) : "r"(addr));
}
__device__ __forceinline__ void ldsm4t(u32* r, u32 addr) {
    asm volatile("ldmatrix.sync.aligned.m8n8.x4.trans.shared.b16 {%0,%1,%2,%3}, [%4];"
                 : "=r"(r[0]), "=r"(r[1]), "=r"(r[2]), "=r"(r[3]) : "r"(addr));
}
__device__ __forceinline__ void mma16816(float* d, const u32* a, u32 b0, u32 b1) {
    asm volatile(
        "mma.sync.aligned.m16n8k16.row.col.f32.bf16.bf16.f32 "
        "{%0,%1,%2,%3}, {%4,%5,%6,%7}, {%8,%9}, {%0,%1,%2,%3};"
        : "+f"(d[0]), "+f"(d[1]), "+f"(d[2]), "+f"(d[3])
        : "r"(a[0]), "r"(a[1]), "r"(a[2]), "r"(a[3]), "r"(b0), "r"(b1));
}
__device__ __forceinline__ u32 cvtbf2(float lo, float hi) {
    u32 r; asm("cvt.rn.bf16x2.f32 %0, %1, %2;" : "=r"(r) : "f"(hi), "f"(lo)); return r;
}
__device__ __forceinline__ u32 resbf2(float lo, float hi, u32 h) {
    __nv_bfloat162 hb = *reinterpret_cast<__nv_bfloat162*>(&h);
    float2 hf = __bfloat1622float2(hb);
    return cvtbf2(lo - hf.x, hi - hf.y);
}

// ---------------------------------------------------------------------------
// split kernels: fp32 -> bf16 hi/mid
// ---------------------------------------------------------------------------
struct __align__(8) BF4 { __nv_bfloat16 a, b, c, d; };

__device__ __forceinline__ void split2(float x, __nv_bfloat16& h, __nv_bfloat16& m) {
    h = __float2bfloat16(x);
    m = __float2bfloat16(x - __bfloat162float(h));
}

__global__ void __launch_bounds__(256) split_hidden(const float* __restrict__ x) {
    size_t i = (size_t)blockIdx.x * 256 + threadIdx.x;
    float4 v = ((const float4*)x)[i];
    BF4 H, M;
    split2(v.x, H.a, M.a);
    split2(v.y, H.b, M.b);
    split2(v.z, H.c, M.c);
    split2(v.w, H.d, M.d);
    ((BF4*)g_Ah)[i] = H;
    ((BF4*)g_Am)[i] = M;
}

__global__ void __launch_bounds__(256) split_w(const float* __restrict__ w) {
    __shared__ float tile[64][65];
    const int n0 = blockIdx.x * 64, k0 = blockIdx.y * 64;
    const int tid = threadIdx.x;
    #pragma unroll
    for (int i = 0; i < 4; i++) {
        int idx = tid + i * 256;
        int r = idx >> 4, c4 = idx & 15;
        float4 v = *(const float4*)&w[(size_t)(k0 + r) * N3 + n0 + c4 * 4];
        tile[r][c4*4+0] = v.x; tile[r][c4*4+1] = v.y;
        tile[r][c4*4+2] = v.z; tile[r][c4*4+3] = v.w;
    }
    __syncthreads();
    #pragma unroll
    for (int i = 0; i < 4; i++) {
        int idx = tid + i * 256;
        int nl = idx >> 4, k4 = idx & 15;
        BF4 H, M;
        split2(tile[k4*4+0][nl], H.a, M.a);
        split2(tile[k4*4+1][nl], H.b, M.b);
        split2(tile[k4*4+2][nl], H.c, M.c);
        split2(tile[k4*4+3][nl], H.d, M.d);
        size_t o = ((size_t)(n0 + nl) * KDIM + k0 + k4 * 4) >> 2;
        ((BF4*)g_Wh)[o] = H;
        ((BF4*)g_Wm)[o] = M;
    }
}

// ---------------------------------------------------------------------------
// mask scan: per batch, list of unmasked key indices + count
// ---------------------------------------------------------------------------
__global__ void __launch_bounds__(1024) scan_mask(const int* __restrict__ mask) {
    __shared__ int sc[1024];
    const int b = blockIdx.x, t = threadIdx.x;
    const int keep = (mask[b * SEQ + t] == 0) ? 1 : 0;
    sc[t] = keep;
    __syncthreads();
    for (int off = 1; off < 1024; off <<= 1) {
        int v = sc[t];
        if (t >= off) v += sc[t - off];
        __syncthreads();
        sc[t] = v;
        __syncthreads();
    }
    if (keep) g_sidx[b * SEQ + sc[t] - 1] = t;
    if (t == 1023) g_cnt[b] = sc[1023];
}

// ---------------------------------------------------------------------------
// compact A-splits per batch: gather unmasked rows, zero-pad to 128 boundary
// ---------------------------------------------------------------------------
__global__ void __launch_bounds__(256) compact_A() {
    const int b = blockIdx.x >> 3, chunk = blockIdx.x & 7;
    const int cnt = g_cnt[b];
    const int padded = (cnt + 127) & ~127;
    const int r0 = chunk * 128;
    if (r0 >= padded) return;
    const int t = threadIdx.x;
    const int arr = t >> 7, u = t & 127;   // 128 uint4 units per 1024-elem row
    const __nv_bfloat16* src = arr ? g_Am : g_Ah;
    __nv_bfloat16* dst = arr ? g_cAm : g_cAh;
    for (int i = 0; i < 128; i++) {
        int r = r0 + i;
        uint4 v = make_uint4(0u, 0u, 0u, 0u);
        if (r < cnt) {
            int s = g_sidx[b * SEQ + r];
            v = *(const uint4*)(src + ((size_t)(b * 1024 + s)) * KDIM + u * 8);
        }
        *(uint4*)(dst + ((size_t)(b * 1024 + r)) * KDIM + u * 8) = v;
    }
}

// ---------------------------------------------------------------------------
// Fused Q-GEMM + KV-GEMM via mma.sync bf16 (2-split, 3 products).
// Blocks [0,512): Q-mode  — all 8192 rows x 1024 Q-cols -> g_Qh/g_Qm.
// Blocks [512,1536): KV-mode — compacted rows x 2048 KV-cols -> g_Kc*/g_Vc*
//   (inactive m-tiles exit immediately).
// K-chunk 32; row = [hi 64B | mid 64B], swizzle u^(row&7). 2-stage, 2 CTA/SM.
// ---------------------------------------------------------------------------
#define SMEM_BUF   32768
#define SMEM_TOTAL (2*SMEM_BUF)
#define NCHUNK     32

__device__ __forceinline__ void load_chunk(u32 base, int tid, int k0, int am0,
                                           const __nv_bfloat16* pAh, const __nv_bfloat16* pAm,
                                           int wbase, bool qmode) {
    #pragma unroll
    for (int j = 0; j < 4; j++) {
        int unit = tid + j * 256;
        int row = unit >> 3, u = unit & 7;
        u32 soff = row * 128 + ((u ^ (row & 7)) << 4);
        size_t goff = (size_t)k0 + ((u & 3) * 8);
        const __nv_bfloat16* sa = (u < 4) ? pAh : pAm;
        const __nv_bfloat16* sw = (u < 4) ? g_Wh : g_Wm;
        int wr = qmode ? (wbase + ((row >> 6) * 192) + (row & 63)) : (wbase + row);
        cp16(base + soff,         sa + (size_t)(am0 + row) * KDIM + goff);
        cp16(base + 16384 + soff, sw + (size_t)wr * KDIM + goff);
    }
}

__global__ void __launch_bounds__(256, 2) qkv_mma(const float* __restrict__ bias) {
    extern __shared__ char smem[];
    const u32 sb = su32(smem);
    const int tid = threadIdx.x;
    const int wid = tid >> 5, lane = tid & 31;
    const int bx = blockIdx.x;
    const bool qmode = bx < 512;

    int bn, bm, wbase;
    const __nv_bfloat16 *pAh, *pAm;
    if (qmode) {
        bn = bx & 7; bm = bx >> 3;            // bn: 8 N-tiles of Q, bm: 64 M-tiles
        pAh = g_Ah; pAm = g_Am;
        wbase = bn * 384;                      // heads 2bn,2bn+1 Q rows in W^T
    } else {
        int b2 = bx - 512;
        bn = b2 & 15; bm = b2 >> 4;            // bn: 16 N-tiles of KV, bm: 64 M-tiles
        const int b = bm >> 3, mt = bm & 7;
        const int padded = (g_cnt[b] + 127) & ~127;
        if (mt * 128 >= padded) return;
        pAh = g_cAh; pAm = g_cAm;
        wbase = bn * 192 + 64;                 // head bn K(64)+V(64) rows in W^T
    }
    const int am0 = bm * 128;
    const int wm = wid >> 2;
    const int wn = wid & 3;

    float acc[4][4][4];
    #pragma unroll
    for (int i = 0; i < 4; i++)
        #pragma unroll
        for (int j = 0; j < 4; j++)
            #pragma unroll
            for (int c = 0; c < 4; c++) acc[i][j][c] = 0.0f;

    const int lrow = (lane & 7) + 8 * ((lane >> 3) & 1);
    const int lu   = lane >> 4;

    load_chunk(sb, tid, 0, am0, pAh, pAm, wbase, qmode);
    cp_commit();

    for (int t = 0; t < NCHUNK; t++) {
        if (t + 1 < NCHUNK) {
            load_chunk(sb + ((t + 1) & 1) * SMEM_BUF, tid, (t + 1) * 32, am0, pAh, pAm, wbase, qmode);
            cp_commit();
            cp_wait1();
        } else {
            cp_wait0();
        }
        __syncthreads();

        const u32 Abuf = sb + (t & 1) * SMEM_BUF;
        const u32 Bbuf = Abuf + 16384;

        #pragma unroll
        for (int kk = 0; kk < 2; kk++) {
            const int uh = 2 * kk + lu;
            const int um = 4 + 2 * kk + lu;
            u32 ah[4][4], am[4][4], bh[2][4], bmf[2][4];
            #pragma unroll
            for (int mt = 0; mt < 4; mt++) {
                int row = wm * 64 + mt * 16 + lrow;
                u32 rbase = row * 128;
                ldsm4(ah[mt], Abuf + rbase + ((uh ^ (row & 7)) << 4));
                ldsm4(am[mt], Abuf + rbase + ((um ^ (row & 7)) << 4));
            }
            #pragma unroll
            for (int ng = 0; ng < 2; ng++) {
                int row = wn * 32 + ng * 16 + lrow;
                u32 rbase = row * 128;
                ldsm4(bh[ng],  Bbuf + rbase + ((uh ^ (row & 7)) << 4));
                ldsm4(bmf[ng], Bbuf + rbase + ((um ^ (row & 7)) << 4));
            }
            #pragma unroll
            for (int mt = 0; mt < 4; mt++) {
                #pragma unroll
                for (int nt = 0; nt < 4; nt++) {
                    const int ng = nt >> 1, sel = nt & 1;
                    mma16816(acc[mt][nt], ah[mt], bh[ng][sel],  bh[ng][sel + 2]);
                    mma16816(acc[mt][nt], ah[mt], bmf[ng][sel], bmf[ng][sel + 2]);
                    mma16816(acc[mt][nt], am[mt], bh[ng][sel],  bh[ng][sel + 2]);
                }
            }
        }
        __syncthreads();
    }

    // --- epilogue: bias + split to bf16 hi/mid + scatter ---
    const int qr = lane >> 2, qc = (lane & 3) * 2;
    #pragma unroll
    for (int nt = 0; nt < 4; nt++) {
        const int coloc = wn * 32 + nt * 8 + qc;
        const int hf = coloc >> 6;
        const int c64 = coloc & 63;
        __nv_bfloat16 *dh, *dm;
        int bcol, head, rowbase;
        if (qmode) {
            head = bn * 2 + hf;
            bcol = head * 192 + c64;
            dh = g_Qh; dm = g_Qm;
            rowbase = (bm >> 3) * (NHEAD * 1024) + head * 1024 + (bm & 7) * 128;
        } else {
            head = bn;
            bcol = head * 192 + 64 + hf * 64 + c64;
            dh = hf ? g_Vch : g_Kch; dm = hf ? g_Vcm : g_Kcm;
            rowbase = (bm >> 3) * (NHEAD * 1024) + head * 1024 + (bm & 7) * 128;
        }
        const float2 bv = *(const float2*)&bias[bcol];
        #pragma unroll
        for (int mt = 0; mt < 4; mt++) {
            #pragma unroll
            for (int half = 0; half < 2; half++) {
                const int mloc = wm * 64 + mt * 16 + qr + half * 8;
                float vx = acc[mt][nt][half * 2 + 0] + bv.x;
                float vy = acc[mt][nt][half * 2 + 1] + bv.y;
                __nv_bfloat162 H, M;
                split2(vx, H.x, M.x);
                split2(vy, H.y, M.y);
                size_t e = ((size_t)(rowbase + mloc)) * 64 + c64;
                *(__nv_bfloat162*)&dh[e] = H;
                *(__nv_bfloat162*)&dm[e] = M;
            }
        }
    }
}

// ---------------------------------------------------------------------------
// Fused attention via mma.sync bf16 over COMPACTED keys.  [R16 structure]
// CTA = 64 q-rows (4 warps x m16), 128 threads.
// smem: QH 8K | QM 8K | 2 x 32K KV stages = 80K.
// ---------------------------------------------------------------------------
#define AT_QH    0
#define AT_QM    8192
#define AT_KV    16384
#define AT_STAGE 32768
#define AT_SMEM  (16384 + 2*32768)   // 81920

__device__ __forceinline__ void at_load_kv(u32 sb, int stg, int tid, size_t base, int kt) {
    u32 st = sb + AT_KV + stg * AT_STAGE;
    size_t goff0 = base + (size_t)kt * 64 * 64;
    #pragma unroll
    for (int r = 0; r < 4; r++) {
        int unit = tid + r * 128;
        int row = unit >> 3, u = unit & 7;
        u32 soff = row * 128 + ((u ^ (row & 7)) << 4);
        size_t g = goff0 + row * 64 + u * 8;
        cp16(st + soff,         g_Kch + g);
        cp16(st + 8192 + soff,  g_Kcm + g);
        cp16(st + 16384 + soff, g_Vch + g);
        cp16(st + 24576 + soff, g_Vcm + g);
    }
}

__global__ void __launch_bounds__(128) attn_mma(float* __restrict__ out) {
    extern __shared__ char smem[];
    const u32 sb = su32(smem);
    const int tid = threadIdx.x;
    const int wid = tid >> 5, lane = tid & 31;
    const int qt = blockIdx.x & 15;
    const int bh = blockIdx.x >> 4;
    const int bb = bh >> 4;
    const int hh = bh & 15;
    const size_t base = (size_t)bh * (SEQ * HDIM);

    const int cnt = g_cnt[bb];
    const int ntiles = (cnt + 63) >> 6;

    const int lrow = (lane & 7) + 8 * ((lane >> 3) & 1);
    const int lu   = lane >> 4;
    const int qr   = lane >> 2;
    const int qc2  = (lane & 3) * 2;

    // prologue: Q tile + KV tile 0 | KV tile 1
    {
        size_t q0 = base + (size_t)qt * 64 * 64;
        #pragma unroll
        for (int r = 0; r < 4; r++) {
            int unit = tid + r * 128;
            int row = unit >> 3, u = unit & 7;
            u32 soff = row * 128 + ((u ^ (row & 7)) << 4);
            size_t g = q0 + row * 64 + u * 8;
            cp16(sb + AT_QH + soff, g_Qh + g);
            cp16(sb + AT_QM + soff, g_Qm + g);
        }
    }
    at_load_kv(sb, 0, tid, base, 0);
    cp_commit();
    if (ntiles > 1) at_load_kv(sb, 1, tid, base, 1);
    cp_commit();
    cp_wait1();
    __syncthreads();

    // preload Q A-frags
    u32 qha[4][4], qma[4][4];
    #pragma unroll
    for (int kk = 0; kk < 4; kk++) {
        int row = wid * 16 + lrow;
        int u = 2 * kk + lu;
        u32 off = row * 128 + ((u ^ (row & 7)) << 4);
        ldsm4(qha[kk], sb + AT_QH + off);
        ldsm4(qma[kk], sb + AT_QM + off);
    }

    float mrun[2] = { -1e30f, -1e30f };
    float lrun[2] = { 0.0f, 0.0f };
    float oacc[8][4];
    #pragma unroll
    for (int n = 0; n < 8; n++)
        #pragma unroll
        for (int c = 0; c < 4; c++) oacc[n][c] = 0.0f;

    for (int kt = 0; kt < ntiles; kt++) {
        const u32 st = sb + AT_KV + (kt & 1) * AT_STAGE;

        // --- S = Q K^T ---
        float p[8][4];
        #pragma unroll
        for (int s = 0; s < 8; s++)
            #pragma unroll
            for (int c = 0; c < 4; c++) p[s][c] = 0.0f;

        #pragma unroll
        for (int kk = 0; kk < 4; kk++) {
            const int uu = 2 * kk + lu;
            u32 kh[4][4], km[4][4];
            #pragma unroll
            for (int kg = 0; kg < 4; kg++) {
                int row = kg * 16 + lrow;
                u32 off = row * 128 + ((uu ^ (row & 7)) << 4);
                ldsm4(kh[kg], st + off);
                ldsm4(km[kg], st + 8192 + off);
            }
            #pragma unroll
            for (int s = 0; s < 8; s++) {
                const int kg = s >> 1, hf = s & 1;
                mma16816(p[s], qha[kk], kh[kg][hf], kh[kg][hf + 2]);
                mma16816(p[s], qha[kk], km[kg][hf], km[kg][hf + 2]);
                mma16816(p[s], qma[kk], kh[kg][hf], kh[kg][hf + 2]);
            }
        }

        // --- scale; pad columns (>= cnt) -> -10000 (exp underflows to 0) ---
        #pragma unroll
        for (int s = 0; s < 8; s++) {
            const int c = kt * 64 + s * 8 + qc2;
            const bool v0 = (c < cnt), v1 = (c + 1 < cnt);
            p[s][0] = v0 ? p[s][0] * 8.0f : -10000.0f;
            p[s][1] = v1 ? p[s][1] * 8.0f : -10000.0f;
            p[s][2] = v0 ? p[s][2] * 8.0f : -10000.0f;
            p[s][3] = v1 ? p[s][3] * 8.0f : -10000.0f;
        }

        // --- online softmax ---
        #pragma unroll
        for (int h = 0; h < 2; h++) {
            float tm = -1e30f;
            #pragma unroll
            for (int s = 0; s < 8; s++)
                tm = fmaxf(tm, fmaxf(p[s][2*h], p[s][2*h + 1]));
            tm = fmaxf(tm, __shfl_xor_sync(0xffffffffu, tm, 1));
            tm = fmaxf(tm, __shfl_xor_sync(0xffffffffu, tm, 2));
            float mnew = fmaxf(mrun[h], tm);
            float ts = 0.0f;
            #pragma unroll
            for (int s = 0; s < 8; s++) {
                p[s][2*h]     = __expf(p[s][2*h]     - mnew);
                p[s][2*h + 1] = __expf(p[s][2*h + 1] - mnew);
                ts += p[s][2*h] + p[s][2*h + 1];
            }
            ts += __shfl_xor_sync(0xffffffffu, ts, 1);
            ts += __shfl_xor_sync(0xffffffffu, ts, 2);
            float alpha = __expf(mrun[h] - mnew);
            lrun[h] = lrun[h] * alpha + ts;
            mrun[h] = mnew;
            #pragma unroll
            for (int n = 0; n < 8; n++) {
                oacc[n][2*h]     *= alpha;
                oacc[n][2*h + 1] *= alpha;
            }
        }

        // --- O += P V ---
        #pragma unroll
        for (int kg = 0; kg < 4; kg++) {
            u32 pha[4], pma[4];
            pha[0] = cvtbf2(p[2*kg][0],     p[2*kg][1]);
            pha[1] = cvtbf2(p[2*kg][2],     p[2*kg][3]);
            pha[2] = cvtbf2(p[2*kg + 1][0], p[2*kg + 1][1]);
            pha[3] = cvtbf2(p[2*kg + 1][2], p[2*kg + 1][3]);
            pma[0] = resbf2(p[2*kg][0],     p[2*kg][1],     pha[0]);
            pma[1] = resbf2(p[2*kg][2],     p[2*kg][3],     pha[1]);
            pma[2] = resbf2(p[2*kg + 1][0], p[2*kg + 1][1], pha[2]);
            pma[3] = resbf2(p[2*kg + 1][2], p[2*kg + 1][3], pha[3]);

            u32 vh[4][4], vm[4][4];
            #pragma unroll
            for (int ng = 0; ng < 4; ng++) {
                int row = kg * 16 + lrow;
                int u = 2 * ng + lu;
                u32 off = row * 128 + ((u ^ (row & 7)) << 4);
                ldsm4t(vh[ng], st + 16384 + off);
                ldsm4t(vm[ng], st + 24576 + off);
            }
            #pragma unroll
            for (int n8 = 0; n8 < 8; n8++) {
                const int ng = n8 >> 1, hf = n8 & 1;
                mma16816(oacc[n8], pha, vh[ng][2*hf], vh[ng][2*hf + 1]);
                mma16816(oacc[n8], pha, vm[ng][2*hf], vm[ng][2*hf + 1]);
                mma16816(oacc[n8], pma, vh[ng][2*hf], vh[ng][2*hf + 1]);
            }
        }

        __syncthreads();
        if (kt + 2 < ntiles) {
            at_load_kv(sb, kt & 1, tid, base, kt + 2);
            cp_commit();
        }
        if (kt + 1 < ntiles) {
            if (kt + 2 < ntiles) cp_wait1(); else cp_wait0();
            __syncthreads();
        }
    }

    // --- epilogue ---
    #pragma unroll
    for (int h = 0; h < 2; h++) {
        float inv = 1.0f / lrun[h];
        int qrow = qt * 64 + wid * 16 + qr + h * 8;
        float* drow = out + ((size_t)(bb * SEQ + qrow)) * HID + hh * 64;
        #pragma unroll
        for (int n8 = 0; n8 < 8; n8++) {
            float2 v;
            v.x = oacc[n8][2*h]     * inv;
            v.y = oacc[n8][2*h + 1] * inv;
            *(float2*)&drow[n8 * 8 + qc2] = v;
        }
    }
}

extern "C" void kernel_launch(void* const* d_in, const int* in_sizes, int n_in,
                              void* d_out, int out_size)
{
    const float* hidden = (const float*)d_in[0];
    const int*   mask   = (const int*)  d_in[1];
    const float* w_qkv  = (const float*)d_in[2];
    const float* b_qkv  = (const float*)d_in[3];
    float* out = (float*)d_out;

    cudaFuncSetAttribute(qkv_mma, cudaFuncAttributeMaxDynamicSharedMemorySize, SMEM_TOTAL);
    cudaFuncSetAttribute(attn_mma, cudaFuncAttributeMaxDynamicSharedMemorySize, AT_SMEM);

    split_hidden<<<MROWS * KDIM / 4 / 256, 256>>>(hidden);
    split_w<<<dim3(N3 / 64, KDIM / 64), 256>>>(w_qkv);
    scan_mask<<<BATCH, 1024>>>(mask);
    compact_A<<<BATCH * 8, 256>>>();
    qkv_mma<<<1536, 256, SMEM_TOTAL>>>(b_qkv);
    attn_mma<<<BATCH * NHEAD * (SEQ / 64), 128, AT_SMEM>>>(out);
}